// round 13
// baseline (speedup 1.0000x reference)
#include <cuda_runtime.h>
#include <math.h>

#define NB 16
#define NN 512
#define NH 64

// ---------------- scratch ----------------
__device__ float g_hidden[NB*NN*64];
__device__ float g_rh[NB*NN*64];
__device__ float g_H1[NB*NN*64];
__device__ float g_H2[NB*NN*64];
__device__ float g_E1[NB*NN*2];
__device__ float g_E2[NB*NN*2];
__device__ float g_z[NB*NN*64];
__device__ float g_nvs[NB*NN*16];
__device__ float g_nvt[NB*NN*16];
__device__ float g_M[NB*NN*NN];
__device__ float g_t1[NB*4*NN*2];
__device__ float g_t2[NB*4*NN*2];
__device__ float g_tar[NB*NN*32];
__device__ float g_gat[NB*NN*2];
__device__ float g_Pa[NB*NN*32];
__device__ float g_Pb[NB*NN*32];
__device__ float g_Pc[NB*NN*32];
__device__ float g_Q1[NB*NN*32];
__device__ float g_Waa[64*32];
__device__ float g_Wbb[64*32];
__device__ float g_Wcc[64*32];

// ---------------- math helpers ----------------
__device__ __forceinline__ float ftanh(float x){            // accurate (gates)
    x = fminf(fmaxf(x, -44.f), 44.f);
    float e = __expf(2.f*x);
    return 1.f - __fdividef(2.f, e + 1.f);
}
__device__ __forceinline__ float ftanh_fast(float x){       // MUFU.TANH (attn/adp)
    float r; asm("tanh.approx.f32 %0, %1;" : "=f"(r) : "f"(x)); return r;
}
__device__ __forceinline__ float fsigm(float x){
    x = fminf(fmaxf(x, -40.f), 40.f);
    return __fdividef(1.f, 1.f + __expf(-x));
}
__device__ __forceinline__ float tf32r(float x){            // round-to-nearest tf32
    unsigned u; asm("cvt.rna.tf32.f32 %0, %1;" : "=r"(u) : "f"(x));
    return __uint_as_float(u);
}
__device__ __forceinline__ float4 tf32r4(float4 v){
    float4 r; r.x=tf32r(v.x); r.y=tf32r(v.y); r.z=tf32r(v.z); r.w=tf32r(v.w); return r;
}

__global__ void k_zero(){
    int i = blockIdx.x*blockDim.x + threadIdx.x;
    if (i < NB*NN*64) g_hidden[i] = 0.f;
}

// combine hyper weights: Wa = W0+.05W1+.05W2, Wb = .95W1+.0475W2, Wc = .9025W2
__global__ void k_wcomb(const float* __restrict__ W1, const float* __restrict__ W2){
    int k = blockIdx.x, c = threadIdx.x;
    const float* W = (c < 16) ? W1 : W2;
    int cc = c & 15;
    float w0 = W[k*16+cc], w1 = W[(64+k)*16+cc], w2 = W[(128+k)*16+cc];
    g_Waa[k*32+c] = w0 + 0.05f*w1 + 0.05f*w2;
    g_Wbb[k*32+c] = 0.95f*w1 + 0.0475f*w2;
    g_Wcc[k*32+c] = 0.9025f*w2;
}

// hidden(64) -> Pa,Pb,Pc (32 each)
__global__ void k_hproj(const float* __restrict__ B1, const float* __restrict__ B2){
    int rbase = blockIdx.x*64, tid = threadIdx.x;
    __shared__ float Hs[64][64];
    __shared__ float Wa[64][32], Wb[64][32], Wc[64][32];
    for (int idx = tid; idx < 64*64; idx += 256)
        Hs[idx>>6][idx&63] = g_hidden[(size_t)(rbase + (idx>>6))*64 + (idx&63)];
    for (int idx = tid; idx < 64*32; idx += 256){
        Wa[idx>>5][idx&31] = g_Waa[idx];
        Wb[idx>>5][idx&31] = g_Wbb[idx];
        Wc[idx>>5][idx&31] = g_Wcc[idx];
    }
    __syncthreads();
    int c = tid & 31, ty = tid >> 5;
    float pa[8] = {}, pb[8] = {}, pc[8] = {};
    #pragma unroll 8
    for (int k = 0; k < 64; k++){
        float wa = Wa[k][c], wb = Wb[k][c], wc = Wc[k][c];
        #pragma unroll
        for (int i = 0; i < 8; i++){
            float h = Hs[ty*8+i][k];
            pa[i] += h*wa; pb[i] += h*wb; pc[i] += h*wc;
        }
    }
    float bias = (c < 16) ? B1[c] : B2[c & 15];
    #pragma unroll
    for (int i = 0; i < 8; i++){
        size_t o = (size_t)(rbase + ty*8 + i)*32 + c;
        g_Pa[o] = pa[i] + bias;
        g_Pb[o] = pb[i];
        g_Pc[o] = pc[i];
    }
}

// ---------------- tf32 tensor-core GCN GEMM ----------------
// Out[b,n,c] = alpha*X0[b,n,c] + beta * sum_v Op[b?,v,n]*Hin[b,v,c]
// Block: 32 rows(n) x C cols, 128 threads (4 warps: wn=warp&1 row-half, wc=warp>>1 col-half).
// mma.m16n8k8 tf32; FNV=1 (C=32): write nvs/nvt instead of Out.
template<int C, int FNV>
__global__ void __launch_bounds__(128)
k_gemm_tc(const float* __restrict__ Op, long opBS,
          const float* __restrict__ Hin, const float* __restrict__ X0,
          float* __restrict__ Out, float alpha, float beta,
          const float* __restrict__ graph, int gstride,
          const float* __restrict__ Wse, const float* __restrict__ bse,
          const float* __restrict__ Wte, const float* __restrict__ bte){
    constexpr int AP = 40;        // As row stride (pad 8 -> conflict-free frags)
    constexpr int BP = C + 8;     // Bs row stride
    constexpr int NCT = C/16;     // n8 c-tiles per warp (4 for C=64, 2 for C=32)
    constexpr int BQ  = C/4;      // float4 per B row
    int b = blockIdx.z, w0 = blockIdx.x*32;
    const float* op  = Op  + (size_t)b*opBS;
    const float* hin = Hin + (size_t)b*NN*C;
    const float* x0  = X0  + (size_t)b*NN*C;
    float*       out = Out + (size_t)b*NN*C;
    __shared__ float As[2][32][AP];   // [k][n]
    __shared__ float Bs[2][32][BP];   // [k][c]
    int tid = threadIdx.x;
    int lane = tid & 31, warp = tid >> 5;
    int g = lane >> 2, tg = lane & 3;
    int wn = warp & 1, wc = warp >> 1;
    float acc[NCT][4] = {};
    float4 ra[2], rb[NCT];

    // prefetch tile 0
    #pragma unroll
    for (int i = 0; i < 2; i++){
        int q = tid + i*128;
        ra[i] = *(const float4*)(op + (size_t)(q>>3)*NN + w0 + (q&7)*4);
    }
    #pragma unroll
    for (int i = 0; i < NCT; i++){
        int q = tid + i*128;
        rb[i] = *(const float4*)(hin + (size_t)(q/BQ)*C + (q%BQ)*4);
    }
    #pragma unroll
    for (int i = 0; i < 2; i++){
        int q = tid + i*128;
        *(float4*)&As[0][q>>3][(q&7)*4] = tf32r4(ra[i]);
    }
    #pragma unroll
    for (int i = 0; i < NCT; i++){
        int q = tid + i*128;
        *(float4*)&Bs[0][q/BQ][(q%BQ)*4] = tf32r4(rb[i]);
    }
    __syncthreads();

    for (int t = 0; t < 16; t++){
        int cur = t & 1;
        if (t < 15){
            int k0 = (t+1)*32;
            #pragma unroll
            for (int i = 0; i < 2; i++){
                int q = tid + i*128;
                ra[i] = *(const float4*)(op + (size_t)(k0 + (q>>3))*NN + w0 + (q&7)*4);
            }
            #pragma unroll
            for (int i = 0; i < NCT; i++){
                int q = tid + i*128;
                rb[i] = *(const float4*)(hin + (size_t)(k0 + q/BQ)*C + (q%BQ)*4);
            }
        }
        #pragma unroll
        for (int s = 0; s < 4; s++){
            int k8 = s*8;
            unsigned a0 = __float_as_uint(As[cur][k8+tg  ][wn*16+g]);
            unsigned a1 = __float_as_uint(As[cur][k8+tg  ][wn*16+g+8]);
            unsigned a2 = __float_as_uint(As[cur][k8+tg+4][wn*16+g]);
            unsigned a3 = __float_as_uint(As[cur][k8+tg+4][wn*16+g+8]);
            #pragma unroll
            for (int j = 0; j < NCT; j++){
                unsigned b0 = __float_as_uint(Bs[cur][k8+tg  ][wc*(C/2)+j*8+g]);
                unsigned b1 = __float_as_uint(Bs[cur][k8+tg+4][wc*(C/2)+j*8+g]);
                asm volatile(
                    "mma.sync.aligned.m16n8k8.row.col.f32.tf32.tf32.f32 "
                    "{%0,%1,%2,%3}, {%4,%5,%6,%7}, {%8,%9}, {%0,%1,%2,%3};\n"
                    : "+f"(acc[j][0]), "+f"(acc[j][1]), "+f"(acc[j][2]), "+f"(acc[j][3])
                    : "r"(a0), "r"(a1), "r"(a2), "r"(a3), "r"(b0), "r"(b1));
            }
        }
        if (t < 15){
            int nb = 1 - cur;
            #pragma unroll
            for (int i = 0; i < 2; i++){
                int q = tid + i*128;
                *(float4*)&As[nb][q>>3][(q&7)*4] = tf32r4(ra[i]);
            }
            #pragma unroll
            for (int i = 0; i < NCT; i++){
                int q = tid + i*128;
                *(float4*)&Bs[nb][q/BQ][(q%BQ)*4] = tf32r4(rb[i]);
            }
            __syncthreads();
        }
    }

    int r0 = w0 + wn*16 + g, r1 = r0 + 8;
    if (!FNV){
        #pragma unroll
        for (int j = 0; j < NCT; j++){
            int cb = wc*(C/2) + j*8 + 2*tg;
            float2 xv = *(const float2*)(x0 + (size_t)r0*C + cb);
            float2 o0 = { alpha*xv.x + beta*acc[j][0], alpha*xv.y + beta*acc[j][1] };
            *(float2*)(out + (size_t)r0*C + cb) = o0;
            float2 xw = *(const float2*)(x0 + (size_t)r1*C + cb);
            float2 o1 = { alpha*xw.x + beta*acc[j][2], alpha*xw.y + beta*acc[j][3] };
            *(float2*)(out + (size_t)r1*C + cb) = o1;
        }
    } else {
        float ga0 = graph[(size_t)b*gstride + r0*2];
        float ga1 = graph[(size_t)b*gstride + r0*2 + 1];
        float gb0 = graph[(size_t)b*gstride + r1*2];
        float gb1 = graph[(size_t)b*gstride + r1*2 + 1];
        #pragma unroll
        for (int j = 0; j < NCT; j++){
            int cb = wc*(C/2) + j*8 + 2*tg;
            #pragma unroll
            for (int q = 0; q < 2; q++){
                int cc = cb + q;
                float tv0 = alpha*x0[(size_t)r0*C + cc] + beta*acc[j][q];
                float tv1 = alpha*x0[(size_t)r1*C + cc] + beta*acc[j][2+q];
                if (cc < 16){
                    float e0 = ga0*Wse[cc] + ga1*Wse[16+cc] + bse[cc];
                    float e1 = gb0*Wse[cc] + gb1*Wse[16+cc] + bse[cc];
                    g_nvs[((size_t)b*NN + r0)*16 + cc] = ftanh(2.f*e0*tv0);
                    g_nvs[((size_t)b*NN + r1)*16 + cc] = ftanh(2.f*e1*tv1);
                } else {
                    int ct = cc - 16;
                    float e0 = ga0*Wte[ct] + ga1*Wte[16+ct] + bte[ct];
                    float e1 = gb0*Wte[ct] + gb1*Wte[16+ct] + bte[ct];
                    g_nvt[((size_t)b*NN + r0)*16 + ct] = ftanh(2.f*e0*tv0);
                    g_nvt[((size_t)b*NN + r1)*16 + ct] = ftanh(2.f*e1*tv1);
                }
            }
        }
    }
}

// ---------------- extra (graph) channel propagation: Out = .05*Xg + .95*M^T In  (C=2) ----------------
__global__ void k_gemmE(const float* __restrict__ M,
                        const float* __restrict__ In, long inBS,
                        const float* __restrict__ Xg, long xBS,
                        float* __restrict__ Out){
    int b = blockIdx.y, w0 = blockIdx.x*64;
    int tid = threadIdx.x;
    int wp = tid & 63, c = (tid>>6)&1, half = tid>>7;
    __shared__ float sh[1024];
    __shared__ float red[128];
    for (int idx = tid; idx < 1024; idx += 256)
        sh[idx] = In[(size_t)b*inBS + idx];
    __syncthreads();
    const float* mp = M + ((size_t)b*512 + half*256)*512 + w0 + wp;
    float acc = 0.f;
    #pragma unroll 8
    for (int v = 0; v < 256; v++)
        acc += mp[(size_t)v*512] * sh[(half*256 + v)*2 + c];
    if (half == 1) red[c*64 + wp] = acc;
    __syncthreads();
    if (half == 0){
        float tot = acc + red[c*64 + wp];
        float x = Xg[(size_t)b*xBS + (size_t)(w0+wp)*2 + c];
        Out[((size_t)b*512 + w0 + wp)*2 + c] = 0.05f*x + 0.95f*tot;
    }
}

// ---------------- adaptive adjacency ----------------
__global__ void k_adp(const float* __restrict__ A){
    int b = blockIdx.y, n0 = blockIdx.x*8;
    int tid = threadIdx.x;
    __shared__ float sn[8][16], tn[8][16];
    __shared__ float vals[8][512];
    __shared__ float wsum[8][8];
    __shared__ float inv[8];
    if (tid < 128){
        int r = tid >> 4, e = tid & 15;
        sn[r][e] = g_nvs[((size_t)b*512 + n0 + r)*16 + e];
        tn[r][e] = g_nvt[((size_t)b*512 + n0 + r)*16 + e];
    }
    __syncthreads();
    float lsum[8] = {};
    #pragma unroll
    for (int mi = 0; mi < 2; mi++){
        int m = tid + mi*256;
        float sm[16], tm[16];
        const float4* sp = (const float4*)(g_nvs + ((size_t)b*512 + m)*16);
        const float4* tp = (const float4*)(g_nvt + ((size_t)b*512 + m)*16);
        #pragma unroll
        for (int q = 0; q < 4; q++){
            float4 v = sp[q]; sm[q*4]=v.x; sm[q*4+1]=v.y; sm[q*4+2]=v.z; sm[q*4+3]=v.w;
            float4 w = tp[q]; tm[q*4]=w.x; tm[q*4+1]=w.y; tm[q*4+2]=w.z; tm[q*4+3]=w.w;
        }
        #pragma unroll
        for (int r = 0; r < 8; r++){
            float d = 0.f;
            #pragma unroll
            for (int e = 0; e < 16; e++) d += sn[r][e]*tm[e] - tn[r][e]*sm[e];
            float v = ftanh_fast(2.f*d);
            v = fmaxf(v, 0.f);
            if (m == n0 + r) v += 1.f;
            vals[r][m] = v; lsum[r] += v;
        }
    }
    #pragma unroll
    for (int r = 0; r < 8; r++){
        float s = lsum[r];
        for (int o = 16; o > 0; o >>= 1) s += __shfl_xor_sync(0xffffffffu, s, o);
        if ((tid & 31) == 0) wsum[r][tid>>5] = s;
    }
    __syncthreads();
    if (tid < 8){
        float s = 0.f;
        #pragma unroll
        for (int w = 0; w < 8; w++) s += wsum[tid][w];
        inv[tid] = __fdividef(1.f, s);
    }
    __syncthreads();
    #pragma unroll
    for (int mi = 0; mi < 2; mi++){
        int m = tid + mi*256;
        #pragma unroll
        for (int r = 0; r < 8; r++)
            g_M[((size_t)b*512 + n0 + r)*512 + m] = vals[r][m]*inv[r] + A[(size_t)(n0+r)*512 + m];
    }
}

// ---------------- z/r (DUAL=1) or c (DUAL=0) projection 198x64, 32-row tiles ----------------
template<int DUAL>
__global__ void __launch_bounds__(128)
k_proj_zrc(const float* __restrict__ W1, const float* __restrict__ B1,
           const float* __restrict__ W2, const float* __restrict__ B2,
           const float* __restrict__ graph, int gstride){
    int rbase = blockIdx.x*32, tid = threadIdx.x;
    __align__(16) __shared__ float As[18][32];
    __align__(16) __shared__ float Bs1[18][64];
    __align__(16) __shared__ float Bs2[(DUAL?18:1)][64];
    int tx = tid & 15, ty = tid >> 4;      // ty 0..7
    float ac1[4][4] = {}, ac2[4][4] = {};
    const float* S0 = DUAL ? g_hidden : g_rh;
    for (int kc = 0; kc < 198; kc += 18){
        for (int idx = tid; idx < 18*32; idx += 128){
            int k = idx >> 5, r = idx & 31;
            int kg = kc + k, seg = kg/66, c = kg - seg*66;
            int row = rbase + r;
            float v;
            if (c < 2){
                if (seg == 0){
                    int bb = row >> 9, n = row & 511;
                    v = graph[(size_t)bb*gstride + n*2 + c];
                } else {
                    v = (seg == 1 ? g_E1 : g_E2)[(size_t)row*2 + c];
                }
            } else {
                const float* Hm = (seg == 0) ? S0 : (seg == 1 ? g_H1 : g_H2);
                v = Hm[(size_t)row*64 + (c-2)];
            }
            As[k][r] = v;
        }
        for (int idx = tid; idx < 18*64; idx += 128){
            int k = idx >> 6, j = idx & 63;
            Bs1[k][j] = W1[(kc+k)*64 + j];
            if (DUAL) Bs2[k][j] = W2[(kc+k)*64 + j];
        }
        __syncthreads();
        #pragma unroll
        for (int k = 0; k < 18; k++){
            float4 a4 = *(const float4*)&As[k][ty*4];
            float4 w1 = *(const float4*)&Bs1[k][tx*4];
            float av[4] = {a4.x,a4.y,a4.z,a4.w};
            float wv[4] = {w1.x,w1.y,w1.z,w1.w};
            #pragma unroll
            for (int i = 0; i < 4; i++)
                #pragma unroll
                for (int j = 0; j < 4; j++)
                    ac1[i][j] += av[i]*wv[j];
            if (DUAL){
                float4 w2 = *(const float4*)&Bs2[k][tx*4];
                float uv[4] = {w2.x,w2.y,w2.z,w2.w};
                #pragma unroll
                for (int i = 0; i < 4; i++)
                    #pragma unroll
                    for (int j = 0; j < 4; j++)
                        ac2[i][j] += av[i]*uv[j];
            }
        }
        __syncthreads();
    }
    #pragma unroll
    for (int i = 0; i < 4; i++){
        int row = rbase + ty*4 + i;
        #pragma unroll
        for (int j = 0; j < 4; j++){
            int col = tx*4 + j;
            if (DUAL){
                float z = fsigm(ac1[i][j] + B1[col]);
                float r = fsigm(ac2[i][j] + B2[col]);
                g_z[(size_t)row*64 + col] = z;
                g_rh[(size_t)row*64 + col] = r * g_hidden[(size_t)row*64 + col];
            } else {
                float cc = ftanh(ac1[i][j] + B1[col]);
                size_t hi = (size_t)row*64 + col;
                float zz = g_z[hi];
                g_hidden[hi] = zz*g_hidden[hi] + (1.f - zz)*cc;
            }
        }
    }
}

// ---------------- attention scores + softmax ----------------
__global__ void k_attn(const float* __restrict__ sample, const float* __restrict__ wq,
                       const float* __restrict__ wk, const float* __restrict__ bias,
                       const float* __restrict__ trans, float* __restrict__ attn){
    int b = blockIdx.z, t = blockIdx.y, n0 = blockIdx.x*8;
    int tid = threadIdx.x;
    __shared__ float ks[512][8];
    __shared__ float qs[8][8];
    __shared__ float sc[8][512];
    __shared__ float wred[8][8];
    __shared__ float rmax[8], rinv[8];
    __shared__ float wkl[16], trl[8];
    if (tid < 16) wkl[tid] = wk[tid];
    if (tid >= 32 && tid < 40) trl[tid-32] = trans[tid-32];
    __syncthreads();
    #pragma unroll
    for (int mi = 0; mi < 2; mi++){
        int m = tid + mi*256;
        size_t si = ((size_t)(b*24 + 20 + t)*512 + m)*2;
        float s0 = sample[si], s1 = sample[si+1];
        #pragma unroll
        for (int d = 0; d < 8; d++) ks[m][d] = s0*wkl[d] + s1*wkl[8+d];
    }
    if (tid < 64){
        int r = tid >> 3, d = tid & 7;
        size_t ti = ((size_t)(b*24 + 23)*512 + n0 + r)*2;
        qs[r][d] = sample[ti]*wq[d] + sample[ti+1]*wq[8+d] + bias[d];
    }
    __syncthreads();
    float lmax[8];
    #pragma unroll
    for (int r = 0; r < 8; r++) lmax[r] = -1e30f;
    #pragma unroll
    for (int mi = 0; mi < 2; mi++){
        int m = tid + mi*256;
        float kk[8];
        #pragma unroll
        for (int d = 0; d < 8; d++) kk[d] = ks[m][d];
        #pragma unroll
        for (int r = 0; r < 8; r++){
            float acc = 0.f;
            #pragma unroll
            for (int d = 0; d < 8; d++) acc += ftanh_fast(qs[r][d] + kk[d]) * trl[d];
            sc[r][m] = acc;
            lmax[r] = fmaxf(lmax[r], acc);
        }
    }
    #pragma unroll
    for (int r = 0; r < 8; r++){
        float v = lmax[r];
        for (int o = 16; o > 0; o >>= 1) v = fmaxf(v, __shfl_xor_sync(0xffffffffu, v, o));
        if ((tid & 31) == 0) wred[r][tid>>5] = v;
    }
    __syncthreads();
    if (tid < 8){
        float v = -1e30f;
        #pragma unroll
        for (int w = 0; w < 8; w++) v = fmaxf(v, wred[tid][w]);
        rmax[tid] = v;
    }
    __syncthreads();
    float lsum[8] = {};
    #pragma unroll
    for (int mi = 0; mi < 2; mi++){
        int m = tid + mi*256;
        #pragma unroll
        for (int r = 0; r < 8; r++){
            float e = __expf(sc[r][m] - rmax[r]);
            sc[r][m] = e; lsum[r] += e;
        }
    }
    __syncthreads();
    #pragma unroll
    for (int r = 0; r < 8; r++){
        float s = lsum[r];
        for (int o = 16; o > 0; o >>= 1) s += __shfl_xor_sync(0xffffffffu, s, o);
        if ((tid & 31) == 0) wred[r][tid>>5] = s;
    }
    __syncthreads();
    if (tid < 8){
        float s = 0.f;
        #pragma unroll
        for (int w = 0; w < 8; w++) s += wred[tid][w];
        rinv[tid] = __fdividef(1.f, s);
    }
    __syncthreads();
    #pragma unroll
    for (int mi = 0; mi < 2; mi++){
        int m = tid + mi*256;
        #pragma unroll
        for (int r = 0; r < 8; r++)
            attn[((size_t)(b*4 + t)*512 + n0 + r)*512 + m] = sc[r][m]*rinv[r];
    }
}

// ---------------- TGN GCN iteration ----------------
__global__ void __launch_bounds__(128)
k_tgn(const float* __restrict__ A, const float* __restrict__ attn,
      const float* __restrict__ sample, const float* __restrict__ Hin,
      float* __restrict__ Out, int first){
    int g = blockIdx.y;
    int w = blockIdx.x*128 + threadIdx.x;
    int b = g >> 2, t = g & 3;
    __shared__ float hx[1024];
    const float* xbase = sample + ((size_t)(b*24 + 20 + t)*512)*2;
    for (int v = threadIdx.x; v < 512; v += 128){
        if (first){ hx[v*2] = xbase[v*2]; hx[v*2+1] = xbase[v*2+1]; }
        else { hx[v*2] = Hin[(size_t)g*1024 + v*2]; hx[v*2+1] = Hin[(size_t)g*1024 + v*2 + 1]; }
    }
    __syncthreads();
    const float* at = attn + (size_t)g*512*512;
    float a0 = 0.f, a1 = 0.f;
    #pragma unroll 4
    for (int v = 0; v < 512; v++){
        float aw = A[(size_t)v*512 + w] + at[(size_t)v*512 + w];
        a0 += hx[v*2]*aw; a1 += hx[v*2+1]*aw;
    }
    Out[(size_t)g*1024 + w*2]     = 0.05f*xbase[w*2]   + 0.95f*a0;
    Out[(size_t)g*1024 + w*2 + 1] = 0.05f*xbase[w*2+1] + 0.95f*a1;
}

// ---------------- TGN output projection + relu + sum_t + gat ----------------
__global__ void k_tgn_out(const float* __restrict__ sample, const float* __restrict__ Wt,
                          const float* __restrict__ bt, const float* __restrict__ Ws,
                          const float* __restrict__ bs, float* __restrict__ out_gat){
    int unit = blockIdx.x*8 + (threadIdx.x >> 5);
    int k = threadIdx.x & 31;
    int b = unit >> 9, n = unit & 511;
    float acc = 0.f;
    #pragma unroll
    for (int t = 0; t < 4; t++){
        int g = b*4 + t;
        size_t xi = ((size_t)(b*24 + 20 + t)*512 + n)*2;
        size_t hi = ((size_t)g*512 + n)*2;
        float o = bt[k]
            + sample[xi]*Wt[k]      + sample[xi+1]*Wt[32+k]
            + g_t1[hi]*Wt[64+k]     + g_t1[hi+1]*Wt[96+k]
            + g_t2[hi]*Wt[128+k]    + g_t2[hi+1]*Wt[160+k];
        acc += fmaxf(o, 0.f);
    }
    g_tar[(size_t)unit*32 + k] = acc;
    float s0 = acc*Ws[k*2], s1 = acc*Ws[k*2+1];
    for (int o = 16; o > 0; o >>= 1){
        s0 += __shfl_xor_sync(0xffffffffu, s0, o);
        s1 += __shfl_xor_sync(0xffffffffu, s1, o);
    }
    if (k == 0){
        float v0 = s0 + bs[0], v1 = s1 + bs[1];
        g_gat[(size_t)unit*2]   = v0; g_gat[(size_t)unit*2+1]   = v1;
        out_gat[(size_t)unit*2] = v0; out_gat[(size_t)unit*2+1] = v1;
    }
}

// ---------------- final projections ----------------
__global__ void k_final(const float* __restrict__ Wl, const float* __restrict__ bl,
                        const float* __restrict__ Wm, const float* __restrict__ bm,
                        float* __restrict__ out_gru, float* __restrict__ out_fin){
    int row = blockIdx.x*256 + threadIdx.x;
    float r0 = bl[0], r1 = bl[1], f0 = bm[0], f1 = bm[1];
    for (int kk = 0; kk < 32; kk++){
        float tv = g_tar[(size_t)row*32 + kk];
        f0 += tv*Wm[kk*2]; f1 += tv*Wm[kk*2+1];
    }
    for (int h = 0; h < 64; h++){
        float hv = g_hidden[(size_t)row*64 + h];
        r0 += hv*Wl[h*2]; r1 += hv*Wl[h*2+1];
        f0 += hv*Wm[(32+h)*2]; f1 += hv*Wm[(32+h)*2+1];
    }
    out_gru[row*2] = r0; out_gru[row*2+1] = r1;
    out_fin[row*2] = f0; out_fin[row*2+1] = f1;
}

// ---------------- host ----------------
extern "C" void kernel_launch(void* const* d_in, const int* in_sizes, int n_in,
                              void* d_out, int out_size){
    const float* sample = (const float*)d_in[0];
    const float* A   = (const float*)d_in[1];
    const float* wq  = (const float*)d_in[2];
    const float* wk  = (const float*)d_in[3];
    const float* ab  = (const float*)d_in[4];
    const float* atr = (const float*)d_in[5];
    const float* Wt  = (const float*)d_in[6];
    const float* bt  = (const float*)d_in[7];
    const float* Wa1 = (const float*)d_in[8];
    const float* ba1 = (const float*)d_in[9];
    const float* Wa2 = (const float*)d_in[10];
    const float* ba2 = (const float*)d_in[11];
    const float* Wse = (const float*)d_in[12];
    const float* bse = (const float*)d_in[13];
    const float* Wte = (const float*)d_in[14];
    const float* bte = (const float*)d_in[15];
    const float* Wgz = (const float*)d_in[16];
    const float* bgz = (const float*)d_in[17];
    const float* Wgr = (const float*)d_in[18];
    const float* bgr = (const float*)d_in[19];
    const float* Wgc = (const float*)d_in[20];
    const float* bgc = (const float*)d_in[21];
    const float* Wsh = (const float*)d_in[22];
    const float* bsh = (const float*)d_in[23];
    const float* Wl  = (const float*)d_in[24];
    const float* bl  = (const float*)d_in[25];
    const float* Wm  = (const float*)d_in[26];
    const float* bm  = (const float*)d_in[27];

    float* out = (float*)d_out;
    float* out_gat  = out;
    float* out_gru  = out + 16384;
    float* out_fin  = out + 32768;
    float* out_attn = out + 49152;

    float *pM, *pH1, *pH2, *pE1, *pE2, *phid, *prh, *pt1, *pt2, *pgat;
    float *pPa, *pPb, *pPc, *pQ1;
    cudaGetSymbolAddress((void**)&pM,   g_M);
    cudaGetSymbolAddress((void**)&pH1,  g_H1);
    cudaGetSymbolAddress((void**)&pH2,  g_H2);
    cudaGetSymbolAddress((void**)&pE1,  g_E1);
    cudaGetSymbolAddress((void**)&pE2,  g_E2);
    cudaGetSymbolAddress((void**)&phid, g_hidden);
    cudaGetSymbolAddress((void**)&prh,  g_rh);
    cudaGetSymbolAddress((void**)&pt1,  g_t1);
    cudaGetSymbolAddress((void**)&pt2,  g_t2);
    cudaGetSymbolAddress((void**)&pgat, g_gat);
    cudaGetSymbolAddress((void**)&pPa,  g_Pa);
    cudaGetSymbolAddress((void**)&pPb,  g_Pb);
    cudaGetSymbolAddress((void**)&pPc,  g_Pc);
    cudaGetSymbolAddress((void**)&pQ1,  g_Q1);

    auto gru = [&](const float* graph, int gstride){
        k_hproj<<<128,256>>>(ba1, ba2);
        k_gemm_tc<32,0><<<dim3(16,1,16),128>>>(A, 0, pPc, pPb, pQ1, 1.f, 1.f,
                                               graph, gstride, Wse, bse, Wte, bte);
        k_gemm_tc<32,1><<<dim3(16,1,16),128>>>(A, 0, pQ1, pPa, pQ1, 1.f, 1.f,
                                               graph, gstride, Wse, bse, Wte, bte);
        k_adp<<<dim3(64,16),256>>>(A);
        k_gemmE<<<dim3(8,16),256>>>(pM, graph, gstride, graph, gstride, pE1);
        k_gemmE<<<dim3(8,16),256>>>(pM, pE1, 1024, graph, gstride, pE2);
        k_gemm_tc<64,0><<<dim3(16,1,16),128>>>(pM, 512L*512, phid, phid, pH1, 0.05f, 0.95f,
                                               graph, gstride, Wse, bse, Wte, bte);
        k_gemm_tc<64,0><<<dim3(16,1,16),128>>>(pM, 512L*512, pH1, phid, pH2, 0.05f, 0.95f,
                                               graph, gstride, Wse, bse, Wte, bte);
        k_proj_zrc<1><<<256,128>>>(Wgz, bgz, Wgr, bgr, graph, gstride);
        k_gemm_tc<64,0><<<dim3(16,1,16),128>>>(pM, 512L*512, prh, prh, pH1, 0.05f, 0.95f,
                                               graph, gstride, Wse, bse, Wte, bte);
        k_gemm_tc<64,0><<<dim3(16,1,16),128>>>(pM, 512L*512, pH1, prh, pH2, 0.05f, 0.95f,
                                               graph, gstride, Wse, bse, Wte, bte);
        k_proj_zrc<0><<<256,128>>>(Wgc, bgc, (const float*)0, (const float*)0,
                                   graph, gstride);
    };

    k_zero<<<2048,256>>>();
    k_wcomb<<<64,32>>>(Wa1, Wa2);
    for (int s = 0; s < 5; s++)
        gru(sample + (size_t)4*s*1024, 24576);

    k_attn<<<dim3(64,4,16),256>>>(sample, wq, wk, ab, atr, out_attn);
    k_tgn<<<dim3(4,64),128>>>(A, out_attn, sample, (const float*)0, pt1, 1);
    k_tgn<<<dim3(4,64),128>>>(A, out_attn, sample, pt1, pt2, 0);
    k_tgn_out<<<1024,256>>>(sample, Wt, bt, Wsh, bsh, out_gat);

    gru(pgat, 1024);
    k_final<<<32,256>>>(Wl, bl, Wm, bm, out_gru, out_fin);
}

// round 14
// speedup vs baseline: 1.2312x; 1.2312x over previous
#include <cuda_runtime.h>
#include <math.h>

#define NB 16
#define NN 512
#define NH 64

// ---------------- scratch ----------------
__device__ float g_hidden[NB*NN*64];
__device__ float g_rh[NB*NN*64];
__device__ float g_H1[NB*NN*64];
__device__ float g_H2[NB*NN*64];
__device__ float g_E1[NB*NN*2];
__device__ float g_E2[NB*NN*2];
__device__ float g_z[NB*NN*64];
__device__ float g_nvs[NB*NN*16];
__device__ float g_nvt[NB*NN*16];
__device__ float g_M[NB*NN*NN];
__device__ float g_t1[NB*4*NN*2];
__device__ float g_t2[NB*4*NN*2];
__device__ float g_tar[NB*NN*32];
__device__ float g_gat[NB*NN*2];
__device__ float g_Pa[NB*NN*32];
__device__ float g_Pb[NB*NN*32];
__device__ float g_Pc[NB*NN*32];
__device__ float g_Q1[NB*NN*32];
__device__ float g_Waa[64*32];
__device__ float g_Wbb[64*32];
__device__ float g_Wcc[64*32];

// ---------------- math helpers ----------------
__device__ __forceinline__ float ftanh(float x){            // accurate (gates)
    x = fminf(fmaxf(x, -44.f), 44.f);
    float e = __expf(2.f*x);
    return 1.f - __fdividef(2.f, e + 1.f);
}
__device__ __forceinline__ float ftanh_fast(float x){       // MUFU.TANH (attn/adp)
    float r; asm("tanh.approx.f32 %0, %1;" : "=f"(r) : "f"(x)); return r;
}
__device__ __forceinline__ float fsigm(float x){
    x = fminf(fmaxf(x, -40.f), 40.f);
    return __fdividef(1.f, 1.f + __expf(-x));
}

__global__ void k_zero(){
    int i = blockIdx.x*blockDim.x + threadIdx.x;
    if (i < NB*NN*64) g_hidden[i] = 0.f;
}

// combine hyper weights: Wa = W0+.05W1+.05W2, Wb = .95W1+.0475W2, Wc = .9025W2
__global__ void k_wcomb(const float* __restrict__ W1, const float* __restrict__ W2){
    int k = blockIdx.x, c = threadIdx.x;
    const float* W = (c < 16) ? W1 : W2;
    int cc = c & 15;
    float w0 = W[k*16+cc], w1 = W[(64+k)*16+cc], w2 = W[(128+k)*16+cc];
    g_Waa[k*32+c] = w0 + 0.05f*w1 + 0.05f*w2;
    g_Wbb[k*32+c] = 0.95f*w1 + 0.0475f*w2;
    g_Wcc[k*32+c] = 0.9025f*w2;
}

// hidden(64) -> Pa,Pb,Pc (32 each)
__global__ void k_hproj(const float* __restrict__ B1, const float* __restrict__ B2){
    int rbase = blockIdx.x*64, tid = threadIdx.x;
    __shared__ float Hs[64][64];
    __shared__ float Wa[64][32], Wb[64][32], Wc[64][32];
    for (int idx = tid; idx < 64*64; idx += 256)
        Hs[idx>>6][idx&63] = g_hidden[(size_t)(rbase + (idx>>6))*64 + (idx&63)];
    for (int idx = tid; idx < 64*32; idx += 256){
        Wa[idx>>5][idx&31] = g_Waa[idx];
        Wb[idx>>5][idx&31] = g_Wbb[idx];
        Wc[idx>>5][idx&31] = g_Wcc[idx];
    }
    __syncthreads();
    int c = tid & 31, ty = tid >> 5;
    float pa[8] = {}, pb[8] = {}, pc[8] = {};
    #pragma unroll 8
    for (int k = 0; k < 64; k++){
        float wa = Wa[k][c], wb = Wb[k][c], wc = Wc[k][c];
        #pragma unroll
        for (int i = 0; i < 8; i++){
            float h = Hs[ty*8+i][k];
            pa[i] += h*wa; pb[i] += h*wb; pc[i] += h*wc;
        }
    }
    float bias = (c < 16) ? B1[c] : B2[c & 15];
    #pragma unroll
    for (int i = 0; i < 8; i++){
        size_t o = (size_t)(rbase + ty*8 + i)*32 + c;
        g_Pa[o] = pa[i] + bias;
        g_Pb[o] = pb[i];
        g_Pc[o] = pc[i];
    }
}

// ---------------- round-8 GCN GEMM: 32-row x full-C tiles, 128 threads, double-buffered BK=32 ----------------
// Out[b,w,c] = alpha*X0[b,w,c] + beta * sum_v Op[b?,v,w]*Hin[b,v,c]
template<int C, int FNV>
__global__ void __launch_bounds__(128)
k_gemm(const float* __restrict__ Op, long opBS,
       const float* __restrict__ Hin, const float* __restrict__ X0,
       float* __restrict__ Out, float alpha, float beta,
       const float* __restrict__ graph, int gstride,
       const float* __restrict__ Wse, const float* __restrict__ bse,
       const float* __restrict__ Wte, const float* __restrict__ bte){
    constexpr int TX  = C/4;       // col groups of 4 (16 for C=64, 8 for C=32)
    constexpr int TYN = 128/TX;    // row groups (8 / 16)
    constexpr int RPT = 32/TYN;    // rows per thread (4 / 2)
    constexpr int NB4 = C/16;      // float4 B loads per thread per tile (4 / 2)
    int b = blockIdx.z, w0 = blockIdx.x*32;
    const float* op  = Op  + (size_t)b*opBS;
    const float* hin = Hin + (size_t)b*NN*C;
    const float* x0  = X0  + (size_t)b*NN*C;
    float*       out = Out + (size_t)b*NN*C;
    __shared__ float As[2][32][32];
    __shared__ float Bs[2][32][C];
    int tid = threadIdx.x;
    int tx = tid % TX, ty = tid / TX;
    float4 ra4[2], rb4[NB4];
    float acc[4][4] = {};

    #pragma unroll
    for (int i = 0; i < 2; i++){
        int idx = tid + i*128;
        ra4[i] = *(const float4*)(op + (size_t)(idx>>3)*NN + w0 + (idx&7)*4);
    }
    #pragma unroll
    for (int i = 0; i < NB4; i++)
        rb4[i] = ((const float4*)hin)[tid + i*128];
    #pragma unroll
    for (int i = 0; i < 2; i++){
        int idx = tid + i*128;
        *(float4*)&As[0][idx>>3][(idx&7)*4] = ra4[i];
    }
    #pragma unroll
    for (int i = 0; i < NB4; i++)
        ((float4*)&Bs[0][0][0])[tid + i*128] = rb4[i];
    __syncthreads();

    for (int t = 0; t < 16; t++){
        int cur = t & 1;
        if (t < 15){
            int k0 = (t+1)*32;
            #pragma unroll
            for (int i = 0; i < 2; i++){
                int idx = tid + i*128;
                ra4[i] = *(const float4*)(op + (size_t)(k0 + (idx>>3))*NN + w0 + (idx&7)*4);
            }
            #pragma unroll
            for (int i = 0; i < NB4; i++)
                rb4[i] = ((const float4*)(hin + (size_t)k0*C))[tid + i*128];
        }
        #pragma unroll
        for (int k = 0; k < 32; k++){
            float av[4];
            if (RPT == 4){
                float4 a = *(const float4*)&As[cur][k][ty*4];
                av[0]=a.x; av[1]=a.y; av[2]=a.z; av[3]=a.w;
            } else {
                float2 a = *(const float2*)&As[cur][k][ty*2];
                av[0]=a.x; av[1]=a.y; av[2]=0.f; av[3]=0.f;
            }
            float4 bv = *(const float4*)&Bs[cur][k][tx*4];
            #pragma unroll
            for (int i = 0; i < RPT; i++){
                acc[i][0] += av[i]*bv.x; acc[i][1] += av[i]*bv.y;
                acc[i][2] += av[i]*bv.z; acc[i][3] += av[i]*bv.w;
            }
        }
        if (t < 15){
            int nb = 1 - cur;
            #pragma unroll
            for (int i = 0; i < 2; i++){
                int idx = tid + i*128;
                *(float4*)&As[nb][idx>>3][(idx&7)*4] = ra4[i];
            }
            #pragma unroll
            for (int i = 0; i < NB4; i++)
                ((float4*)&Bs[nb][0][0])[tid + i*128] = rb4[i];
            __syncthreads();
        }
    }

    #pragma unroll
    for (int i = 0; i < RPT; i++){
        int n = w0 + ty*RPT + i;
        size_t ro = (size_t)n*C;
        if (!FNV){
            #pragma unroll
            for (int j = 0; j < 4; j++){
                int cc = tx*4 + j;
                out[ro + cc] = alpha*x0[ro + cc] + beta*acc[i][j];
            }
        } else {
            float g0 = graph[(size_t)b*gstride + n*2];
            float g1 = graph[(size_t)b*gstride + n*2 + 1];
            #pragma unroll
            for (int j = 0; j < 4; j++){
                int cc = tx*4 + j;
                float tv = alpha*x0[(size_t)n*C + cc] + beta*acc[i][j];
                if (cc < 16){
                    float es = g0*Wse[cc] + g1*Wse[16+cc] + bse[cc];
                    g_nvs[((size_t)b*NN + n)*16 + cc] = ftanh(2.f*es*tv);
                } else {
                    int ct = cc - 16;
                    float et = g0*Wte[ct] + g1*Wte[16+ct] + bte[ct];
                    g_nvt[((size_t)b*NN + n)*16 + ct] = ftanh(2.f*et*tv);
                }
            }
        }
    }
}

// ---------------- FUSED: gemm64 (blocks x<16) + graph-channel E propagation (blocks x>=16) ----------------
// gemm part: Out[b,n,c] = .05*X0 + .95 * sum_v M[b,v,n]*Hin[b,v,c]   (C=64)
// E part:    Eout[b,n,c2] = .05*Xg[b,n,c2] + .95 * sum_v M[b,v,n]*Ein[b,v,c2]  (c2=0,1)
__global__ void __launch_bounds__(128)
k_gemm64E(const float* __restrict__ M,
          const float* __restrict__ Hin, const float* __restrict__ X0,
          float* __restrict__ Out,
          const float* __restrict__ Ein, long einBS,
          const float* __restrict__ Xg, long xgBS,
          float* __restrict__ Eout){
    int b = blockIdx.z;
    int tid = threadIdx.x;
    if (blockIdx.x >= 16){
        // ---- E part ----
        __shared__ float sh[1024];
        int w0e = (blockIdx.x - 16)*64;
        for (int idx = tid; idx < 1024; idx += 128)
            sh[idx] = Ein[(size_t)b*einBS + idx];
        __syncthreads();
        int wp = tid & 63, c = tid >> 6;
        const float* mp = M + (size_t)b*NN*NN + w0e + wp;
        float acc = 0.f;
        #pragma unroll 8
        for (int v = 0; v < 512; v++)
            acc += mp[(size_t)v*512] * sh[v*2 + c];
        float x = Xg[(size_t)b*xgBS + (size_t)(w0e + wp)*2 + c];
        Eout[((size_t)b*NN + w0e + wp)*2 + c] = 0.05f*x + 0.95f*acc;
        return;
    }
    // ---- gemm64 part (round-8 config) ----
    constexpr int C = 64;
    int w0 = blockIdx.x*32;
    const float* op  = M   + (size_t)b*NN*NN;
    const float* hin = Hin + (size_t)b*NN*C;
    const float* x0  = X0  + (size_t)b*NN*C;
    float*       out = Out + (size_t)b*NN*C;
    __shared__ float As[2][32][32];
    __shared__ float Bs[2][32][C];
    int tx = tid % 16, ty = tid / 16;
    float4 ra4[2], rb4[4];
    float acc[4][4] = {};

    #pragma unroll
    for (int i = 0; i < 2; i++){
        int idx = tid + i*128;
        ra4[i] = *(const float4*)(op + (size_t)(idx>>3)*NN + w0 + (idx&7)*4);
    }
    #pragma unroll
    for (int i = 0; i < 4; i++)
        rb4[i] = ((const float4*)hin)[tid + i*128];
    #pragma unroll
    for (int i = 0; i < 2; i++){
        int idx = tid + i*128;
        *(float4*)&As[0][idx>>3][(idx&7)*4] = ra4[i];
    }
    #pragma unroll
    for (int i = 0; i < 4; i++)
        ((float4*)&Bs[0][0][0])[tid + i*128] = rb4[i];
    __syncthreads();

    for (int t = 0; t < 16; t++){
        int cur = t & 1;
        if (t < 15){
            int k0 = (t+1)*32;
            #pragma unroll
            for (int i = 0; i < 2; i++){
                int idx = tid + i*128;
                ra4[i] = *(const float4*)(op + (size_t)(k0 + (idx>>3))*NN + w0 + (idx&7)*4);
            }
            #pragma unroll
            for (int i = 0; i < 4; i++)
                rb4[i] = ((const float4*)(hin + (size_t)k0*C))[tid + i*128];
        }
        #pragma unroll
        for (int k = 0; k < 32; k++){
            float4 a = *(const float4*)&As[cur][k][ty*4];
            float av[4] = {a.x, a.y, a.z, a.w};
            float4 bv = *(const float4*)&Bs[cur][k][tx*4];
            #pragma unroll
            for (int i = 0; i < 4; i++){
                acc[i][0] += av[i]*bv.x; acc[i][1] += av[i]*bv.y;
                acc[i][2] += av[i]*bv.z; acc[i][3] += av[i]*bv.w;
            }
        }
        if (t < 15){
            int nb = 1 - cur;
            #pragma unroll
            for (int i = 0; i < 2; i++){
                int idx = tid + i*128;
                *(float4*)&As[nb][idx>>3][(idx&7)*4] = ra4[i];
            }
            #pragma unroll
            for (int i = 0; i < 4; i++)
                ((float4*)&Bs[nb][0][0])[tid + i*128] = rb4[i];
            __syncthreads();
        }
    }

    #pragma unroll
    for (int i = 0; i < 4; i++){
        int n = w0 + ty*4 + i;
        size_t ro = (size_t)n*C;
        #pragma unroll
        for (int j = 0; j < 4; j++){
            int cc = tx*4 + j;
            out[ro + cc] = 0.05f*x0[ro + cc] + 0.95f*acc[i][j];
        }
    }
}

// ---------------- adaptive adjacency ----------------
__global__ void k_adp(const float* __restrict__ A){
    int b = blockIdx.y, n0 = blockIdx.x*8;
    int tid = threadIdx.x;
    __shared__ float sn[8][16], tn[8][16];
    __shared__ float vals[8][512];
    __shared__ float wsum[8][8];
    __shared__ float inv[8];
    if (tid < 128){
        int r = tid >> 4, e = tid & 15;
        sn[r][e] = g_nvs[((size_t)b*512 + n0 + r)*16 + e];
        tn[r][e] = g_nvt[((size_t)b*512 + n0 + r)*16 + e];
    }
    __syncthreads();
    float lsum[8] = {};
    #pragma unroll
    for (int mi = 0; mi < 2; mi++){
        int m = tid + mi*256;
        float sm[16], tm[16];
        const float4* sp = (const float4*)(g_nvs + ((size_t)b*512 + m)*16);
        const float4* tp = (const float4*)(g_nvt + ((size_t)b*512 + m)*16);
        #pragma unroll
        for (int q = 0; q < 4; q++){
            float4 v = sp[q]; sm[q*4]=v.x; sm[q*4+1]=v.y; sm[q*4+2]=v.z; sm[q*4+3]=v.w;
            float4 w = tp[q]; tm[q*4]=w.x; tm[q*4+1]=w.y; tm[q*4+2]=w.z; tm[q*4+3]=w.w;
        }
        #pragma unroll
        for (int r = 0; r < 8; r++){
            float d = 0.f;
            #pragma unroll
            for (int e = 0; e < 16; e++) d += sn[r][e]*tm[e] - tn[r][e]*sm[e];
            float v = ftanh_fast(2.f*d);
            v = fmaxf(v, 0.f);
            if (m == n0 + r) v += 1.f;
            vals[r][m] = v; lsum[r] += v;
        }
    }
    #pragma unroll
    for (int r = 0; r < 8; r++){
        float s = lsum[r];
        for (int o = 16; o > 0; o >>= 1) s += __shfl_xor_sync(0xffffffffu, s, o);
        if ((tid & 31) == 0) wsum[r][tid>>5] = s;
    }
    __syncthreads();
    if (tid < 8){
        float s = 0.f;
        #pragma unroll
        for (int w = 0; w < 8; w++) s += wsum[tid][w];
        inv[tid] = __fdividef(1.f, s);
    }
    __syncthreads();
    #pragma unroll
    for (int mi = 0; mi < 2; mi++){
        int m = tid + mi*256;
        #pragma unroll
        for (int r = 0; r < 8; r++)
            g_M[((size_t)b*512 + n0 + r)*512 + m] = vals[r][m]*inv[r] + A[(size_t)(n0+r)*512 + m];
    }
}

// ---------------- z/r (DUAL=1) or c (DUAL=0) projection 198x64, 32-row tiles ----------------
template<int DUAL>
__global__ void __launch_bounds__(128)
k_proj_zrc(const float* __restrict__ W1, const float* __restrict__ B1,
           const float* __restrict__ W2, const float* __restrict__ B2,
           const float* __restrict__ graph, int gstride){
    int rbase = blockIdx.x*32, tid = threadIdx.x;
    __align__(16) __shared__ float As[18][32];
    __align__(16) __shared__ float Bs1[18][64];
    __align__(16) __shared__ float Bs2[(DUAL?18:1)][64];
    int tx = tid & 15, ty = tid >> 4;      // ty 0..7
    float ac1[4][4] = {}, ac2[4][4] = {};
    const float* S0 = DUAL ? g_hidden : g_rh;
    for (int kc = 0; kc < 198; kc += 18){
        for (int idx = tid; idx < 18*32; idx += 128){
            int k = idx >> 5, r = idx & 31;
            int kg = kc + k, seg = kg/66, c = kg - seg*66;
            int row = rbase + r;
            float v;
            if (c < 2){
                if (seg == 0){
                    int bb = row >> 9, n = row & 511;
                    v = graph[(size_t)bb*gstride + n*2 + c];
                } else {
                    v = (seg == 1 ? g_E1 : g_E2)[(size_t)row*2 + c];
                }
            } else {
                const float* Hm = (seg == 0) ? S0 : (seg == 1 ? g_H1 : g_H2);
                v = Hm[(size_t)row*64 + (c-2)];
            }
            As[k][r] = v;
        }
        for (int idx = tid; idx < 18*64; idx += 128){
            int k = idx >> 6, j = idx & 63;
            Bs1[k][j] = W1[(kc+k)*64 + j];
            if (DUAL) Bs2[k][j] = W2[(kc+k)*64 + j];
        }
        __syncthreads();
        #pragma unroll
        for (int k = 0; k < 18; k++){
            float4 a4 = *(const float4*)&As[k][ty*4];
            float4 w1 = *(const float4*)&Bs1[k][tx*4];
            float av[4] = {a4.x,a4.y,a4.z,a4.w};
            float wv[4] = {w1.x,w1.y,w1.z,w1.w};
            #pragma unroll
            for (int i = 0; i < 4; i++)
                #pragma unroll
                for (int j = 0; j < 4; j++)
                    ac1[i][j] += av[i]*wv[j];
            if (DUAL){
                float4 w2 = *(const float4*)&Bs2[k][tx*4];
                float uv[4] = {w2.x,w2.y,w2.z,w2.w};
                #pragma unroll
                for (int i = 0; i < 4; i++)
                    #pragma unroll
                    for (int j = 0; j < 4; j++)
                        ac2[i][j] += av[i]*uv[j];
            }
        }
        __syncthreads();
    }
    #pragma unroll
    for (int i = 0; i < 4; i++){
        int row = rbase + ty*4 + i;
        #pragma unroll
        for (int j = 0; j < 4; j++){
            int col = tx*4 + j;
            if (DUAL){
                float z = fsigm(ac1[i][j] + B1[col]);
                float r = fsigm(ac2[i][j] + B2[col]);
                g_z[(size_t)row*64 + col] = z;
                g_rh[(size_t)row*64 + col] = r * g_hidden[(size_t)row*64 + col];
            } else {
                float cc = ftanh(ac1[i][j] + B1[col]);
                size_t hi = (size_t)row*64 + col;
                float zz = g_z[hi];
                g_hidden[hi] = zz*g_hidden[hi] + (1.f - zz)*cc;
            }
        }
    }
}

// ---------------- attention scores + softmax ----------------
__global__ void k_attn(const float* __restrict__ sample, const float* __restrict__ wq,
                       const float* __restrict__ wk, const float* __restrict__ bias,
                       const float* __restrict__ trans, float* __restrict__ attn){
    int b = blockIdx.z, t = blockIdx.y, n0 = blockIdx.x*8;
    int tid = threadIdx.x;
    __shared__ float ks[512][8];
    __shared__ float qs[8][8];
    __shared__ float sc[8][512];
    __shared__ float wred[8][8];
    __shared__ float rmax[8], rinv[8];
    __shared__ float wkl[16], trl[8];
    if (tid < 16) wkl[tid] = wk[tid];
    if (tid >= 32 && tid < 40) trl[tid-32] = trans[tid-32];
    __syncthreads();
    #pragma unroll
    for (int mi = 0; mi < 2; mi++){
        int m = tid + mi*256;
        size_t si = ((size_t)(b*24 + 20 + t)*512 + m)*2;
        float s0 = sample[si], s1 = sample[si+1];
        #pragma unroll
        for (int d = 0; d < 8; d++) ks[m][d] = s0*wkl[d] + s1*wkl[8+d];
    }
    if (tid < 64){
        int r = tid >> 3, d = tid & 7;
        size_t ti = ((size_t)(b*24 + 23)*512 + n0 + r)*2;
        qs[r][d] = sample[ti]*wq[d] + sample[ti+1]*wq[8+d] + bias[d];
    }
    __syncthreads();
    float lmax[8];
    #pragma unroll
    for (int r = 0; r < 8; r++) lmax[r] = -1e30f;
    #pragma unroll
    for (int mi = 0; mi < 2; mi++){
        int m = tid + mi*256;
        float kk[8];
        #pragma unroll
        for (int d = 0; d < 8; d++) kk[d] = ks[m][d];
        #pragma unroll
        for (int r = 0; r < 8; r++){
            float acc = 0.f;
            #pragma unroll
            for (int d = 0; d < 8; d++) acc += ftanh_fast(qs[r][d] + kk[d]) * trl[d];
            sc[r][m] = acc;
            lmax[r] = fmaxf(lmax[r], acc);
        }
    }
    #pragma unroll
    for (int r = 0; r < 8; r++){
        float v = lmax[r];
        for (int o = 16; o > 0; o >>= 1) v = fmaxf(v, __shfl_xor_sync(0xffffffffu, v, o));
        if ((tid & 31) == 0) wred[r][tid>>5] = v;
    }
    __syncthreads();
    if (tid < 8){
        float v = -1e30f;
        #pragma unroll
        for (int w = 0; w < 8; w++) v = fmaxf(v, wred[tid][w]);
        rmax[tid] = v;
    }
    __syncthreads();
    float lsum[8] = {};
    #pragma unroll
    for (int mi = 0; mi < 2; mi++){
        int m = tid + mi*256;
        #pragma unroll
        for (int r = 0; r < 8; r++){
            float e = __expf(sc[r][m] - rmax[r]);
            sc[r][m] = e; lsum[r] += e;
        }
    }
    __syncthreads();
    #pragma unroll
    for (int r = 0; r < 8; r++){
        float s = lsum[r];
        for (int o = 16; o > 0; o >>= 1) s += __shfl_xor_sync(0xffffffffu, s, o);
        if ((tid & 31) == 0) wred[r][tid>>5] = s;
    }
    __syncthreads();
    if (tid < 8){
        float s = 0.f;
        #pragma unroll
        for (int w = 0; w < 8; w++) s += wred[tid][w];
        rinv[tid] = __fdividef(1.f, s);
    }
    __syncthreads();
    #pragma unroll
    for (int mi = 0; mi < 2; mi++){
        int m = tid + mi*256;
        #pragma unroll
        for (int r = 0; r < 8; r++)
            attn[((size_t)(b*4 + t)*512 + n0 + r)*512 + m] = sc[r][m]*rinv[r];
    }
}

// ---------------- TGN GCN iteration ----------------
__global__ void __launch_bounds__(128)
k_tgn(const float* __restrict__ A, const float* __restrict__ attn,
      const float* __restrict__ sample, const float* __restrict__ Hin,
      float* __restrict__ Out, int first){
    int g = blockIdx.y;
    int w = blockIdx.x*128 + threadIdx.x;
    int b = g >> 2, t = g & 3;
    __shared__ float hx[1024];
    const float* xbase = sample + ((size_t)(b*24 + 20 + t)*512)*2;
    for (int v = threadIdx.x; v < 512; v += 128){
        if (first){ hx[v*2] = xbase[v*2]; hx[v*2+1] = xbase[v*2+1]; }
        else { hx[v*2] = Hin[(size_t)g*1024 + v*2]; hx[v*2+1] = Hin[(size_t)g*1024 + v*2 + 1]; }
    }
    __syncthreads();
    const float* at = attn + (size_t)g*512*512;
    float a0 = 0.f, a1 = 0.f;
    #pragma unroll 4
    for (int v = 0; v < 512; v++){
        float aw = A[(size_t)v*512 + w] + at[(size_t)v*512 + w];
        a0 += hx[v*2]*aw; a1 += hx[v*2+1]*aw;
    }
    Out[(size_t)g*1024 + w*2]     = 0.05f*xbase[w*2]   + 0.95f*a0;
    Out[(size_t)g*1024 + w*2 + 1] = 0.05f*xbase[w*2+1] + 0.95f*a1;
}

// ---------------- TGN output projection + relu + sum_t + gat ----------------
__global__ void k_tgn_out(const float* __restrict__ sample, const float* __restrict__ Wt,
                          const float* __restrict__ bt, const float* __restrict__ Ws,
                          const float* __restrict__ bs, float* __restrict__ out_gat){
    int unit = blockIdx.x*8 + (threadIdx.x >> 5);
    int k = threadIdx.x & 31;
    int b = unit >> 9, n = unit & 511;
    float acc = 0.f;
    #pragma unroll
    for (int t = 0; t < 4; t++){
        int g = b*4 + t;
        size_t xi = ((size_t)(b*24 + 20 + t)*512 + n)*2;
        size_t hi = ((size_t)g*512 + n)*2;
        float o = bt[k]
            + sample[xi]*Wt[k]      + sample[xi+1]*Wt[32+k]
            + g_t1[hi]*Wt[64+k]     + g_t1[hi+1]*Wt[96+k]
            + g_t2[hi]*Wt[128+k]    + g_t2[hi+1]*Wt[160+k];
        acc += fmaxf(o, 0.f);
    }
    g_tar[(size_t)unit*32 + k] = acc;
    float s0 = acc*Ws[k*2], s1 = acc*Ws[k*2+1];
    for (int o = 16; o > 0; o >>= 1){
        s0 += __shfl_xor_sync(0xffffffffu, s0, o);
        s1 += __shfl_xor_sync(0xffffffffu, s1, o);
    }
    if (k == 0){
        float v0 = s0 + bs[0], v1 = s1 + bs[1];
        g_gat[(size_t)unit*2]   = v0; g_gat[(size_t)unit*2+1]   = v1;
        out_gat[(size_t)unit*2] = v0; out_gat[(size_t)unit*2+1] = v1;
    }
}

// ---------------- final projections ----------------
__global__ void k_final(const float* __restrict__ Wl, const float* __restrict__ bl,
                        const float* __restrict__ Wm, const float* __restrict__ bm,
                        float* __restrict__ out_gru, float* __restrict__ out_fin){
    int row = blockIdx.x*256 + threadIdx.x;
    float r0 = bl[0], r1 = bl[1], f0 = bm[0], f1 = bm[1];
    for (int kk = 0; kk < 32; kk++){
        float tv = g_tar[(size_t)row*32 + kk];
        f0 += tv*Wm[kk*2]; f1 += tv*Wm[kk*2+1];
    }
    for (int h = 0; h < 64; h++){
        float hv = g_hidden[(size_t)row*64 + h];
        r0 += hv*Wl[h*2]; r1 += hv*Wl[h*2+1];
        f0 += hv*Wm[(32+h)*2]; f1 += hv*Wm[(32+h)*2+1];
    }
    out_gru[row*2] = r0; out_gru[row*2+1] = r1;
    out_fin[row*2] = f0; out_fin[row*2+1] = f1;
}

// ---------------- host ----------------
extern "C" void kernel_launch(void* const* d_in, const int* in_sizes, int n_in,
                              void* d_out, int out_size){
    const float* sample = (const float*)d_in[0];
    const float* A   = (const float*)d_in[1];
    const float* wq  = (const float*)d_in[2];
    const float* wk  = (const float*)d_in[3];
    const float* ab  = (const float*)d_in[4];
    const float* atr = (const float*)d_in[5];
    const float* Wt  = (const float*)d_in[6];
    const float* bt  = (const float*)d_in[7];
    const float* Wa1 = (const float*)d_in[8];
    const float* ba1 = (const float*)d_in[9];
    const float* Wa2 = (const float*)d_in[10];
    const float* ba2 = (const float*)d_in[11];
    const float* Wse = (const float*)d_in[12];
    const float* bse = (const float*)d_in[13];
    const float* Wte = (const float*)d_in[14];
    const float* bte = (const float*)d_in[15];
    const float* Wgz = (const float*)d_in[16];
    const float* bgz = (const float*)d_in[17];
    const float* Wgr = (const float*)d_in[18];
    const float* bgr = (const float*)d_in[19];
    const float* Wgc = (const float*)d_in[20];
    const float* bgc = (const float*)d_in[21];
    const float* Wsh = (const float*)d_in[22];
    const float* bsh = (const float*)d_in[23];
    const float* Wl  = (const float*)d_in[24];
    const float* bl  = (const float*)d_in[25];
    const float* Wm  = (const float*)d_in[26];
    const float* bm  = (const float*)d_in[27];

    float* out = (float*)d_out;
    float* out_gat  = out;
    float* out_gru  = out + 16384;
    float* out_fin  = out + 32768;
    float* out_attn = out + 49152;

    float *pM, *pH1, *pH2, *pE1, *pE2, *phid, *prh, *pt1, *pt2, *pgat;
    float *pPa, *pPb, *pPc, *pQ1;
    cudaGetSymbolAddress((void**)&pM,   g_M);
    cudaGetSymbolAddress((void**)&pH1,  g_H1);
    cudaGetSymbolAddress((void**)&pH2,  g_H2);
    cudaGetSymbolAddress((void**)&pE1,  g_E1);
    cudaGetSymbolAddress((void**)&pE2,  g_E2);
    cudaGetSymbolAddress((void**)&phid, g_hidden);
    cudaGetSymbolAddress((void**)&prh,  g_rh);
    cudaGetSymbolAddress((void**)&pt1,  g_t1);
    cudaGetSymbolAddress((void**)&pt2,  g_t2);
    cudaGetSymbolAddress((void**)&pgat, g_gat);
    cudaGetSymbolAddress((void**)&pPa,  g_Pa);
    cudaGetSymbolAddress((void**)&pPb,  g_Pb);
    cudaGetSymbolAddress((void**)&pPc,  g_Pc);
    cudaGetSymbolAddress((void**)&pQ1,  g_Q1);

    auto gru = [&](const float* graph, int gstride){
        k_hproj<<<128,256>>>(ba1, ba2);
        k_gemm<32,0><<<dim3(16,1,16),128>>>(A, 0, pPc, pPb, pQ1, 1.f, 1.f,
                                            graph, gstride, Wse, bse, Wte, bte);
        k_gemm<32,1><<<dim3(16,1,16),128>>>(A, 0, pQ1, pPa, pQ1, 1.f, 1.f,
                                            graph, gstride, Wse, bse, Wte, bte);
        k_adp<<<dim3(64,16),256>>>(A);
        // fused: gemm64(h1) + E1 propagation
        k_gemm64E<<<dim3(24,1,16),128>>>(pM, phid, phid, pH1,
                                         graph, (long)gstride, graph, (long)gstride, pE1);
        // fused: gemm64(h2) + E2 propagation
        k_gemm64E<<<dim3(24,1,16),128>>>(pM, pH1, phid, pH2,
                                         pE1, 1024L, graph, (long)gstride, pE2);
        k_proj_zrc<1><<<256,128>>>(Wgz, bgz, Wgr, bgr, graph, gstride);
        k_gemm<64,0><<<dim3(16,1,16),128>>>(pM, 512L*512, prh, prh, pH1, 0.05f, 0.95f,
                                            graph, gstride, Wse, bse, Wte, bte);
        k_gemm<64,0><<<dim3(16,1,16),128>>>(pM, 512L*512, pH1, prh, pH2, 0.05f, 0.95f,
                                            graph, gstride, Wse, bse, Wte, bte);
        k_proj_zrc<0><<<256,128>>>(Wgc, bgc, (const float*)0, (const float*)0,
                                   graph, gstride);
    };

    k_zero<<<2048,256>>>();
    k_wcomb<<<64,32>>>(Wa1, Wa2);
    for (int s = 0; s < 5; s++)
        gru(sample + (size_t)4*s*1024, 24576);

    k_attn<<<dim3(64,4,16),256>>>(sample, wq, wk, ab, atr, out_attn);
    k_tgn<<<dim3(4,64),128>>>(A, out_attn, sample, (const float*)0, pt1, 1);
    k_tgn<<<dim3(4,64),128>>>(A, out_attn, sample, pt1, pt2, 0);
    k_tgn_out<<<1024,256>>>(sample, Wt, bt, Wsh, bsh, out_gat);

    gru(pgat, 1024);
    k_final<<<32,256>>>(Wl, bl, Wm, bm, out_gru, out_fin);
}